// round 11
// baseline (speedup 1.0000x reference)
#include <cuda_runtime.h>
#include <cuda_bf16.h>
#include <math.h>
#include <stdint.h>

#define B_  32
#define T_  64
#define V_  32000
#define D_  512
#define E_  1024
#define H_  1024
#define G4  4096      // 4*H
#define TB  2048      // T*B

// ---------------- device scratch (no allocations allowed) ----------------
__device__ float d_enc_pre[B_ * G4];                  // 0.5 MB
__device__ float d_pre[TB * G4];                      // 32 MB
__device__ float d_hx[(T_ + 1) * B_ * H_];            // 8.5 MB
__device__ unsigned g_bar;
__device__ __nv_bfloat16 d_Ah[TB * H_];               // 4 MB  hx hi
__device__ __nv_bfloat16 d_Al[TB * H_];               // 4 MB  hx lo
__device__ __nv_bfloat16 d_Bh[(size_t)V_ * H_];       // 64 MB W_fc hi
__device__ __nv_bfloat16 d_Bl[(size_t)V_ * H_];       // 64 MB W_fc lo

// ======================= PTX helpers (base-target, no 'a' features) ======
__device__ __forceinline__ uint32_t smem_u32(const void* p) {
    uint32_t a;
    asm("{ .reg .u64 t; cvta.to.shared.u64 t, %1; cvt.u32.u64 %0, t; }"
        : "=r"(a) : "l"(p));
    return a;
}
__device__ __forceinline__ void ldsm_x4(uint32_t& r0, uint32_t& r1,
                                        uint32_t& r2, uint32_t& r3, uint32_t a) {
    asm volatile("ldmatrix.sync.aligned.m8n8.x4.shared.b16 {%0,%1,%2,%3}, [%4];"
                 : "=r"(r0), "=r"(r1), "=r"(r2), "=r"(r3) : "r"(a));
}
__device__ __forceinline__ void mma16816(float* c,
    uint32_t a0, uint32_t a1, uint32_t a2, uint32_t a3, uint32_t b0, uint32_t b1) {
    asm volatile("mma.sync.aligned.m16n8k16.row.col.f32.bf16.bf16.f32 "
                 "{%0,%1,%2,%3}, {%4,%5,%6,%7}, {%8,%9}, {%0,%1,%2,%3};"
                 : "+f"(c[0]), "+f"(c[1]), "+f"(c[2]), "+f"(c[3])
                 : "r"(a0), "r"(a1), "r"(a2), "r"(a3), "r"(b0), "r"(b1));
}
// packed fp32x2 FMA (Blackwell base ISA; ptxas never auto-emits FFMA2)
__device__ __forceinline__ void ffma2(uint64_t& d, uint64_t a, uint64_t b) {
    asm("fma.rn.f32x2 %0, %1, %2, %0;" : "+l"(d) : "l"(a), "l"(b));
}
__device__ __forceinline__ uint64_t splat2(float a) {
    uint64_t r;
    asm("mov.b64 %0, {%1, %1};" : "=l"(r) : "f"(a));
    return r;
}
__device__ __forceinline__ float2 unpack2(uint64_t v) {
    float2 f;
    asm("mov.b64 {%0, %1}, %2;" : "=f"(f.x), "=f"(f.y) : "l"(v));
    return f;
}

// ---------------- init: zero hx slot 0 + barrier (every replay) ----------
__global__ void init_state() {
    int i = blockIdx.x * 256 + threadIdx.x;
    if (i < B_ * H_) d_hx[i] = 0.f;
    if (i == 0) g_bar = 0u;
}

// ---------------- W_fc fp32 -> (hi, lo) bf16 split -----------------------
__global__ __launch_bounds__(256) void conv_wfc(const float* __restrict__ W)
{
    size_t i = (size_t)blockIdx.x * 256 + threadIdx.x;   // float4 index
    float4 v = ((const float4*)W)[i];
    __nv_bfloat16 h0 = __float2bfloat16(v.x);
    __nv_bfloat16 h1 = __float2bfloat16(v.y);
    __nv_bfloat16 h2 = __float2bfloat16(v.z);
    __nv_bfloat16 h3 = __float2bfloat16(v.w);
    __nv_bfloat16 l0 = __float2bfloat16(v.x - __bfloat162float(h0));
    __nv_bfloat16 l1 = __float2bfloat16(v.y - __bfloat162float(h1));
    __nv_bfloat16 l2 = __float2bfloat16(v.z - __bfloat162float(h2));
    __nv_bfloat16 l3 = __float2bfloat16(v.w - __bfloat162float(h3));
    struct bf4 { __nv_bfloat16 a, b, c, d; };
    *(bf4*)(d_Bh + 4 * i) = bf4{h0, h1, h2, h3};
    *(bf4*)(d_Bl + 4 * i) = bf4{l0, l1, l2, l3};
}

// ---------------- enc_pre[b,j] = b_ih[j]+b_hh[j] + sum_e enc[b,e]*W_ih[j,e]
__global__ __launch_bounds__(256) void enc_pre_kernel(
    const float* __restrict__ enc, const float* __restrict__ Wih,
    const float* __restrict__ bih, const float* __restrict__ bhh)
{
    __shared__ float As[32][36];
    __shared__ float Bs[32][36];
    int tid = threadIdx.x;
    int j0  = blockIdx.x * 32;
    int lr  = tid >> 3, lk = (tid & 7) * 4;
    int col = tid & 31, rg = (tid >> 5) * 4;
    float acc[4] = {0.f, 0.f, 0.f, 0.f};

    for (int k0 = 0; k0 < E_; k0 += 32) {
        float4 av = *(const float4*)(enc + lr * E_ + k0 + lk);
        float4 bv = *(const float4*)(Wih + (size_t)(j0 + lr) * (E_ + D_) + k0 + lk);
        As[lk+0][lr] = av.x; As[lk+1][lr] = av.y; As[lk+2][lr] = av.z; As[lk+3][lr] = av.w;
        Bs[lk+0][lr] = bv.x; Bs[lk+1][lr] = bv.y; Bs[lk+2][lr] = bv.z; Bs[lk+3][lr] = bv.w;
        __syncthreads();
#pragma unroll
        for (int kk = 0; kk < 32; kk++) {
            float4 a = *(const float4*)&As[kk][rg];
            float  b = Bs[kk][col];
            acc[0] += a.x * b; acc[1] += a.y * b; acc[2] += a.z * b; acc[3] += a.w * b;
        }
        __syncthreads();
    }
    float bias = bih[j0 + col] + bhh[j0 + col];
#pragma unroll
    for (int i = 0; i < 4; i++)
        d_enc_pre[(rg + i) * G4 + j0 + col] = acc[i] + bias;
}

// ---------------- pre = emb[gather] @ W_ih[:,E:].T + enc_pre --------------
__global__ __launch_bounds__(256, 2) void pre_gemm_big(
    const float* __restrict__ emb, const int* __restrict__ gt,
    const float* __restrict__ Wih)
{
    __shared__ float As[16][132];
    __shared__ float Bs[16][132];
    int tid = threadIdx.x;
    int m0 = blockIdx.x * 128, n0 = blockIdx.y * 128;
    int lr = tid >> 2, lk4 = (tid & 3) * 4;

    int mA0 = m0 + lr, mA1 = m0 + lr + 64;
    int tok0 = gt[(mA0 & 31) * T_ + (mA0 >> 5)];
    int tok1 = gt[(mA1 & 31) * T_ + (mA1 >> 5)];
    const float* Ap0 = emb + (size_t)tok0 * D_ + lk4;
    const float* Ap1 = emb + (size_t)tok1 * D_ + lk4;
    const float* Bp0 = Wih + (size_t)(n0 + lr)      * (E_ + D_) + E_ + lk4;
    const float* Bp1 = Wih + (size_t)(n0 + lr + 64) * (E_ + D_) + E_ + lk4;

    int rm = (tid >> 4) * 8, cn = (tid & 15) * 8;
    uint64_t accp[8][4];                 // rows x packed col-pairs
#pragma unroll
    for (int i = 0; i < 8; i++)
#pragma unroll
        for (int j = 0; j < 4; j++) accp[i][j] = 0ull;

    float4 a0v = *(const float4*)(Ap0);
    float4 a1v = *(const float4*)(Ap1);
    float4 b0v = *(const float4*)(Bp0);
    float4 b1v = *(const float4*)(Bp1);

    for (int k0 = 0; k0 < D_; k0 += 16) {
        As[lk4+0][lr]    = a0v.x; As[lk4+1][lr]    = a0v.y;
        As[lk4+2][lr]    = a0v.z; As[lk4+3][lr]    = a0v.w;
        As[lk4+0][lr+64] = a1v.x; As[lk4+1][lr+64] = a1v.y;
        As[lk4+2][lr+64] = a1v.z; As[lk4+3][lr+64] = a1v.w;
        Bs[lk4+0][lr]    = b0v.x; Bs[lk4+1][lr]    = b0v.y;
        Bs[lk4+2][lr]    = b0v.z; Bs[lk4+3][lr]    = b0v.w;
        Bs[lk4+0][lr+64] = b1v.x; Bs[lk4+1][lr+64] = b1v.y;
        Bs[lk4+2][lr+64] = b1v.z; Bs[lk4+3][lr+64] = b1v.w;
        __syncthreads();

        if (k0 + 16 < D_) {
            a0v = *(const float4*)(Ap0 + k0 + 16);
            a1v = *(const float4*)(Ap1 + k0 + 16);
            b0v = *(const float4*)(Bp0 + k0 + 16);
            b1v = *(const float4*)(Bp1 + k0 + 16);
        }

#pragma unroll
        for (int kk = 0; kk < 16; kk++) {
            float4 x0 = *(const float4*)&As[kk][rm];
            float4 x1 = *(const float4*)&As[kk][rm + 4];
            ulonglong2 yb0 = *(const ulonglong2*)&Bs[kk][cn];
            ulonglong2 yb1 = *(const ulonglong2*)&Bs[kk][cn + 4];
            uint64_t bp0 = yb0.x, bp1 = yb0.y, bp2 = yb1.x, bp3 = yb1.y;
            float av[8] = {x0.x, x0.y, x0.z, x0.w, x1.x, x1.y, x1.z, x1.w};
#pragma unroll
            for (int i = 0; i < 8; i++) {
                uint64_t s = splat2(av[i]);
                ffma2(accp[i][0], s, bp0);
                ffma2(accp[i][1], s, bp1);
                ffma2(accp[i][2], s, bp2);
                ffma2(accp[i][3], s, bp3);
            }
        }
        __syncthreads();
    }

#pragma unroll
    for (int i = 0; i < 8; i++) {
        int mm = m0 + rm + i;
        float4 e0 = *(const float4*)&d_enc_pre[(mm & 31) * G4 + n0 + cn];
        float4 e1 = *(const float4*)&d_enc_pre[(mm & 31) * G4 + n0 + cn + 4];
        float2 p0 = unpack2(accp[i][0]);
        float2 p1 = unpack2(accp[i][1]);
        float2 p2 = unpack2(accp[i][2]);
        float2 p3 = unpack2(accp[i][3]);
        float4 r0 = { p0.x + e0.x, p0.y + e0.y, p1.x + e0.z, p1.y + e0.w };
        float4 r1 = { p2.x + e1.x, p2.y + e1.y, p3.x + e1.z, p3.y + e1.w };
        *(float4*)&d_pre[(size_t)mm * G4 + n0 + cn]     = r0;
        *(float4*)&d_pre[(size_t)mm * G4 + n0 + cn + 4] = r1;
    }
}

// ---------------- persistent recurrence, 512 threads, packed f32x2 --------
__global__ __launch_bounds__(512, 1) void rec_persist(const float* __restrict__ Whh)
{
    extern __shared__ float smem[];
    float* s_hx = smem;             // [32][1024]  128KB
    float* red  = smem + 32768;     // [32][16][32] 64KB

    int tid = threadIdx.x;
    int col = tid & 31;             // gate column within block (g*8+hh)
    int kg  = tid >> 5;             // K-slice 0..15 (64 k each)
    int g   = col >> 3, hh = col & 7;
    int hbase = blockIdx.x * 8;
    int jcol = g * H_ + hbase + hh;

    // W_hh slice packed as fp32 pairs: 64 floats = 16 x ulonglong2
    ulonglong2 w2[16];
    const ulonglong2* wp = (const ulonglong2*)(Whh + (size_t)jcol * H_) + kg * 16;
#pragma unroll
    for (int k = 0; k < 16; k++) w2[k] = wp[k];

    int b_own = tid >> 3, hh_own = tid & 7;   // valid for tid<256
    int hcol_own = hbase + hh_own;
    float creg = 0.f;

    for (int t = 0; t < T_; t++) {
        const float4* src = (const float4*)(d_hx + (size_t)t * (B_ * H_));
        float4* dst = (float4*)s_hx;
#pragma unroll
        for (int i = 0; i < 16; i++) dst[tid + i * 512] = src[tid + i * 512];
        __syncthreads();

#pragma unroll 2
        for (int b = 0; b < 32; b++) {
            const ulonglong2* hrow = (const ulonglong2*)(s_hx + b * H_ + kg * 64);
            uint64_t acc01 = 0ull, acc23 = 0ull;   // packed (+0,+0)
#pragma unroll
            for (int k = 0; k < 16; k++) {
                ulonglong2 h = hrow[k];
                ffma2(acc01, w2[k].x, h.x);
                ffma2(acc23, w2[k].y, h.y);
            }
            float2 s01 = unpack2(acc01);
            float2 s23 = unpack2(acc23);
            red[b * 512 + kg * 32 + col] = (s01.x + s01.y) + (s23.x + s23.y);
        }
        __syncthreads();

        if (tid < 256) {
            float gi = 0.f, gf = 0.f, gg = 0.f, go = 0.f;
#pragma unroll
            for (int kk = 0; kk < 16; kk++) {
                const float* r = red + b_own * 512 + kk * 32;
                gi += r[hh_own];      gf += r[8  + hh_own];
                gg += r[16 + hh_own]; go += r[24 + hh_own];
            }
            const float* pp = d_pre + ((size_t)(t * B_ + b_own)) * G4 + hcol_own;
            gi += pp[0]; gf += pp[H_]; gg += pp[2 * H_]; go += pp[3 * H_];
            float si = 1.f / (1.f + expf(-gi));
            float sf = 1.f / (1.f + expf(-gf));
            float so = 1.f / (1.f + expf(-go));
            creg = sf * creg + si * tanhf(gg);
            float hn = so * tanhf(creg);
            d_hx[(size_t)(t + 1) * (B_ * H_) + b_own * H_ + hcol_own] = hn;
            __nv_bfloat16 ah = __float2bfloat16(hn);
            __nv_bfloat16 al = __float2bfloat16(hn - __bfloat162float(ah));
            size_t arow = (size_t)(t * B_ + b_own) * H_ + hcol_own;
            d_Ah[arow] = ah; d_Al[arow] = al;
        }

        __threadfence();
        __syncthreads();
        if (tid == 0) {
            atomicAdd(&g_bar, 1u);
            unsigned target = 128u * (unsigned)(t + 1);
            while (*((volatile unsigned*)&g_bar) < target) { }
        }
        __syncthreads();
    }
}

// ---------------- tensor logits via mma.sync (bf16 hi/lo split) -----------
// out = Ah@Bh^T + Al@Bh^T + Ah@Bl^T + b_fc.
// CTA 128x256, 8 warps as 2m x 4n, warp tile 64x64 (mi4 x ni8).
// BK=32, double-buffered dynamic smem, reg prefetch, 1 sync/k-tile.
#define PAD_  40
#define ATILE (128 * PAD_)       // bf16 elems per A stage
#define BTILE (256 * PAD_)       // bf16 elems per B stage
__global__ __launch_bounds__(256) void logits_mma(
    const float* __restrict__ bfc, float* __restrict__ out)
{
    extern __shared__ __align__(16) __nv_bfloat16 dsm[];
    __nv_bfloat16* sA = dsm;                 // [2][ATILE]
    __nv_bfloat16* sB = dsm + 2 * ATILE;     // [2][BTILE]

    int tid = threadIdx.x, lane = tid & 31, w = tid >> 5;
    int wm = w & 1, wn = w >> 1;             // 2m x 4n
    int m0 = blockIdx.x * 128, n0 = blockIdx.y * 256;

    float c[4][8][4];
#pragma unroll
    for (int mi = 0; mi < 4; mi++)
#pragma unroll
        for (int ni = 0; ni < 8; ni++)
#pragma unroll
            for (int q = 0; q < 4; q++) c[mi][ni][q] = 0.f;

    // loaders: A 128 rows x 32 cols (2x16B per thread), B 256 rows x 32 cols
    int laR = tid >> 1, laC = (tid & 1) * 16;   // A: row, col(bf16)

    uint4 pa[2], pb[4];
    {
#pragma unroll
        for (int i = 0; i < 2; i++)
            pa[i] = *(const uint4*)(d_Ah + (size_t)(m0 + laR) * H_ + laC + i * 8);
#pragma unroll
        for (int j = 0; j < 4; j++)
            pb[j] = *(const uint4*)(d_Bh + (size_t)(n0 + tid) * H_ + j * 8);
    }

    // ldsm lane addressing (r10-proven formulas)
    int a_row_l = wm * 64 + (lane & 15);
    int a_col_l = (lane >> 4) * 8;
    int b_row_l = wn * 64 + ((lane >> 4) & 1) * 8 + (lane & 7);
    int b_col_l = ((lane >> 3) & 1) * 8;

    int buf = 0;
    for (int it = 0; it < 96; it++) {
        // store prefetched tile
        __nv_bfloat16* sAb = sA + buf * ATILE;
        __nv_bfloat16* sBb = sB + buf * BTILE;
#pragma unroll
        for (int i = 0; i < 2; i++)
            *(uint4*)(&sAb[laR * PAD_ + laC + i * 8]) = pa[i];
#pragma unroll
        for (int j = 0; j < 4; j++)
            *(uint4*)(&sBb[tid * PAD_ + j * 8]) = pb[j];
        __syncthreads();

        // prefetch next k-tile while computing
        if (it + 1 < 96) {
            int nit = it + 1;
            int seg = nit >> 5;                 // 0..2
            int k0  = (nit & 31) * 32;
            const __nv_bfloat16* Ag = (seg == 1) ? d_Al : d_Ah;
            const __nv_bfloat16* Bg = (seg == 2) ? d_Bl : d_Bh;
#pragma unroll
            for (int i = 0; i < 2; i++)
                pa[i] = *(const uint4*)(Ag + (size_t)(m0 + laR) * H_ + k0 + laC + i * 8);
#pragma unroll
            for (int j = 0; j < 4; j++)
                pb[j] = *(const uint4*)(Bg + (size_t)(n0 + tid) * H_ + k0 + j * 8);
        }

        // compute: 2 k16 steps
#pragma unroll
        for (int ks = 0; ks < 2; ks++) {
            uint32_t af[4][4];
#pragma unroll
            for (int mi = 0; mi < 4; mi++) {
                uint32_t a = smem_u32(
                    &sAb[(a_row_l + mi * 16) * PAD_ + ks * 16 + a_col_l]);
                ldsm_x4(af[mi][0], af[mi][1], af[mi][2], af[mi][3], a);
            }
#pragma unroll
            for (int np = 0; np < 4; np++) {
                uint32_t b0, b1, b2, b3;
                uint32_t ba = smem_u32(
                    &sBb[(b_row_l + np * 16) * PAD_ + ks * 16 + b_col_l]);
                ldsm_x4(b0, b1, b2, b3, ba);
#pragma unroll
                for (int mi = 0; mi < 4; mi++) {
                    mma16816(c[mi][np * 2],     af[mi][0], af[mi][1], af[mi][2], af[mi][3], b0, b1);
                    mma16816(c[mi][np * 2 + 1], af[mi][0], af[mi][1], af[mi][2], af[mi][3], b2, b3);
                }
            }
        }
        buf ^= 1;
    }

    // epilogue: acc m16n8 -> (row lane>>2 [+8], col (lane&3)*2 [+1])
#pragma unroll
    for (int mi = 0; mi < 4; mi++) {
#pragma unroll
        for (int ni = 0; ni < 8; ni++) {
            int row = m0 + wm * 64 + mi * 16 + (lane >> 2);
            int col = n0 + wn * 64 + ni * 8 + (lane & 3) * 2;
            float2 bb = *(const float2*)&bfc[col];
            float2 r0 = { c[mi][ni][0] + bb.x, c[mi][ni][1] + bb.y };
            float2 r1 = { c[mi][ni][2] + bb.x, c[mi][ni][3] + bb.y };
            *(float2*)&out[(size_t)row * V_ + col]       = r0;
            *(float2*)&out[(size_t)(row + 8) * V_ + col] = r1;
        }
    }
}

// ---------------- argmax over V per (t,b); predic[b,t] = first max ---------
__global__ __launch_bounds__(256) void argmax_kernel(
    const float* __restrict__ logits, float* __restrict__ pred)
{
    int m = blockIdx.x;                       // m = t*B + b
    const float4* row = (const float4*)(logits + (size_t)m * V_);
    int tid = threadIdx.x;
    float best = -3.402823466e38f;
    int   bi   = 0;
    for (int i = tid; i < V_ / 4; i += 256) {
        float4 v = row[i];
        int j = i * 4;
        if (v.x > best) { best = v.x; bi = j; }
        if (v.y > best) { best = v.y; bi = j + 1; }
        if (v.z > best) { best = v.z; bi = j + 2; }
        if (v.w > best) { best = v.w; bi = j + 3; }
    }
    __shared__ float sv[256];
    __shared__ int   si[256];
    sv[tid] = best; si[tid] = bi;
    __syncthreads();
    for (int s = 128; s > 0; s >>= 1) {
        if (tid < s) {
            if (sv[tid + s] > sv[tid] ||
                (sv[tid + s] == sv[tid] && si[tid + s] < si[tid])) {
                sv[tid] = sv[tid + s]; si[tid] = si[tid + s];
            }
        }
        __syncthreads();
    }
    if (tid == 0) {
        int t = m >> 5, b = m & 31;
        pred[b * T_ + t] = (float)si[0];
    }
}

// ------------------------------------------------------------------------
extern "C" void kernel_launch(void* const* d_in, const int* in_sizes, int n_in,
                              void* d_out, int out_size)
{
    const float* encoder = (const float*)d_in[0];
    const int*   gtruths = (const int*)  d_in[1];
    const float* emb     = (const float*)d_in[2];
    const float* W_ih    = (const float*)d_in[3];
    const float* W_hh    = (const float*)d_in[4];
    const float* b_ih    = (const float*)d_in[5];
    const float* b_hh    = (const float*)d_in[6];
    const float* W_fc    = (const float*)d_in[7];
    const float* b_fc    = (const float*)d_in[8];
    float* out = (float*)d_out;

    static int attr_set = 0;
    if (!attr_set) {
        cudaFuncSetAttribute(rec_persist,
                             cudaFuncAttributeMaxDynamicSharedMemorySize, 196608);
        cudaFuncSetAttribute(logits_mma,
                             cudaFuncAttributeMaxDynamicSharedMemorySize,
                             (2 * ATILE + 2 * BTILE) * 2);
        attr_set = 1;
    }

    init_state<<<(B_ * H_ + 255) / 256, 256>>>();
    conv_wfc<<<(int)(((size_t)V_ * H_ / 4) / 256), 256>>>(W_fc);
    enc_pre_kernel<<<G4 / 32, 256>>>(encoder, W_ih, b_ih, b_hh);
    pre_gemm_big<<<dim3(TB / 128, G4 / 128), 256>>>(emb, gtruths, W_ih);
    rec_persist<<<128, 512, 196608>>>(W_hh);
    logits_mma<<<dim3(TB / 128, V_ / 256), 256,
                 (2 * ATILE + 2 * BTILE) * 2>>>(b_fc, out);
    if (out_size >= TB * V_ + TB)
        argmax_kernel<<<TB, 256>>>(out, out + (size_t)TB * V_);
}

// round 12
// speedup vs baseline: 1.1992x; 1.1992x over previous
#include <cuda_runtime.h>
#include <cuda_bf16.h>
#include <math.h>
#include <stdint.h>

#define B_  32
#define T_  64
#define V_  32000
#define D_  512
#define E_  1024
#define H_  1024
#define G4  4096      // 4*H
#define TB  2048      // T*B

// ---------------- device scratch (no allocations allowed) ----------------
__device__ float d_enc_pre[B_ * G4];                  // 0.5 MB
__device__ float d_pre[TB * G4];                      // 32 MB
__device__ float d_hx[(T_ + 1) * B_ * H_];            // 8.5 MB
__device__ unsigned g_bar;
__device__ __nv_bfloat16 d_Ah[TB * H_];               // 4 MB  hx hi
__device__ __nv_bfloat16 d_Al[TB * H_];               // 4 MB  hx lo
__device__ __nv_bfloat16 d_Bh[(size_t)V_ * H_];       // 64 MB W_fc hi
__device__ __nv_bfloat16 d_Bl[(size_t)V_ * H_];       // 64 MB W_fc lo
__device__ unsigned long long d_amax[TB];             // packed (val, ~col)

// ======================= PTX helpers (base-target, no 'a' features) ======
__device__ __forceinline__ uint32_t smem_u32(const void* p) {
    uint32_t a;
    asm("{ .reg .u64 t; cvta.to.shared.u64 t, %1; cvt.u32.u64 %0, t; }"
        : "=r"(a) : "l"(p));
    return a;
}
__device__ __forceinline__ void ldsm_x4(uint32_t& r0, uint32_t& r1,
                                        uint32_t& r2, uint32_t& r3, uint32_t a) {
    asm volatile("ldmatrix.sync.aligned.m8n8.x4.shared.b16 {%0,%1,%2,%3}, [%4];"
                 : "=r"(r0), "=r"(r1), "=r"(r2), "=r"(r3) : "r"(a));
}
__device__ __forceinline__ void mma16816(float* c,
    uint32_t a0, uint32_t a1, uint32_t a2, uint32_t a3, uint32_t b0, uint32_t b1) {
    asm volatile("mma.sync.aligned.m16n8k16.row.col.f32.bf16.bf16.f32 "
                 "{%0,%1,%2,%3}, {%4,%5,%6,%7}, {%8,%9}, {%0,%1,%2,%3};"
                 : "+f"(c[0]), "+f"(c[1]), "+f"(c[2]), "+f"(c[3])
                 : "r"(a0), "r"(a1), "r"(a2), "r"(a3), "r"(b0), "r"(b1));
}
// packed fp32x2 FMA (Blackwell base ISA; ptxas never auto-emits FFMA2)
__device__ __forceinline__ void ffma2(uint64_t& d, uint64_t a, uint64_t b) {
    asm("fma.rn.f32x2 %0, %1, %2, %0;" : "+l"(d) : "l"(a), "l"(b));
}
__device__ __forceinline__ uint64_t splat2(float a) {
    uint64_t r;
    asm("mov.b64 %0, {%1, %1};" : "=l"(r) : "f"(a));
    return r;
}
__device__ __forceinline__ float2 unpack2(uint64_t v) {
    float2 f;
    asm("mov.b64 {%0, %1}, %2;" : "=f"(f.x), "=f"(f.y) : "l"(v));
    return f;
}
// monotone float->uint (order-preserving)
__device__ __forceinline__ uint32_t fmono(float f) {
    uint32_t u = __float_as_uint(f);
    return (u & 0x80000000u) ? ~u : (u | 0x80000000u);
}

// ---------------- init: zero hx slot 0 + barrier + argmax (every replay) --
__global__ void init_state() {
    int i = blockIdx.x * 256 + threadIdx.x;
    if (i < B_ * H_) d_hx[i] = 0.f;
    if (i < TB) d_amax[i] = 0ull;
    if (i == 0) g_bar = 0u;
}

// ---------------- W_fc fp32 -> (hi, lo) bf16 split -----------------------
__global__ __launch_bounds__(256) void conv_wfc(const float* __restrict__ W)
{
    size_t i = (size_t)blockIdx.x * 256 + threadIdx.x;   // float4 index
    float4 v = ((const float4*)W)[i];
    __nv_bfloat16 h0 = __float2bfloat16(v.x);
    __nv_bfloat16 h1 = __float2bfloat16(v.y);
    __nv_bfloat16 h2 = __float2bfloat16(v.z);
    __nv_bfloat16 h3 = __float2bfloat16(v.w);
    __nv_bfloat16 l0 = __float2bfloat16(v.x - __bfloat162float(h0));
    __nv_bfloat16 l1 = __float2bfloat16(v.y - __bfloat162float(h1));
    __nv_bfloat16 l2 = __float2bfloat16(v.z - __bfloat162float(h2));
    __nv_bfloat16 l3 = __float2bfloat16(v.w - __bfloat162float(h3));
    struct bf4 { __nv_bfloat16 a, b, c, d; };
    *(bf4*)(d_Bh + 4 * i) = bf4{h0, h1, h2, h3};
    *(bf4*)(d_Bl + 4 * i) = bf4{l0, l1, l2, l3};
}

// ---------------- enc_pre[b,j] = b_ih[j]+b_hh[j] + sum_e enc[b,e]*W_ih[j,e]
__global__ __launch_bounds__(256) void enc_pre_kernel(
    const float* __restrict__ enc, const float* __restrict__ Wih,
    const float* __restrict__ bih, const float* __restrict__ bhh)
{
    __shared__ float As[32][36];
    __shared__ float Bs[32][36];
    int tid = threadIdx.x;
    int j0  = blockIdx.x * 32;
    int lr  = tid >> 3, lk = (tid & 7) * 4;
    int col = tid & 31, rg = (tid >> 5) * 4;
    float acc[4] = {0.f, 0.f, 0.f, 0.f};

    for (int k0 = 0; k0 < E_; k0 += 32) {
        float4 av = *(const float4*)(enc + lr * E_ + k0 + lk);
        float4 bv = *(const float4*)(Wih + (size_t)(j0 + lr) * (E_ + D_) + k0 + lk);
        As[lk+0][lr] = av.x; As[lk+1][lr] = av.y; As[lk+2][lr] = av.z; As[lk+3][lr] = av.w;
        Bs[lk+0][lr] = bv.x; Bs[lk+1][lr] = bv.y; Bs[lk+2][lr] = bv.z; Bs[lk+3][lr] = bv.w;
        __syncthreads();
#pragma unroll
        for (int kk = 0; kk < 32; kk++) {
            float4 a = *(const float4*)&As[kk][rg];
            float  b = Bs[kk][col];
            acc[0] += a.x * b; acc[1] += a.y * b; acc[2] += a.z * b; acc[3] += a.w * b;
        }
        __syncthreads();
    }
    float bias = bih[j0 + col] + bhh[j0 + col];
#pragma unroll
    for (int i = 0; i < 4; i++)
        d_enc_pre[(rg + i) * G4 + j0 + col] = acc[i] + bias;
}

// ---------------- pre = emb[gather] @ W_ih[:,E:].T + enc_pre --------------
__global__ __launch_bounds__(256, 2) void pre_gemm_big(
    const float* __restrict__ emb, const int* __restrict__ gt,
    const float* __restrict__ Wih)
{
    __shared__ float As[16][132];
    __shared__ float Bs[16][132];
    int tid = threadIdx.x;
    int m0 = blockIdx.x * 128, n0 = blockIdx.y * 128;
    int lr = tid >> 2, lk4 = (tid & 3) * 4;

    int mA0 = m0 + lr, mA1 = m0 + lr + 64;
    int tok0 = gt[(mA0 & 31) * T_ + (mA0 >> 5)];
    int tok1 = gt[(mA1 & 31) * T_ + (mA1 >> 5)];
    const float* Ap0 = emb + (size_t)tok0 * D_ + lk4;
    const float* Ap1 = emb + (size_t)tok1 * D_ + lk4;
    const float* Bp0 = Wih + (size_t)(n0 + lr)      * (E_ + D_) + E_ + lk4;
    const float* Bp1 = Wih + (size_t)(n0 + lr + 64) * (E_ + D_) + E_ + lk4;

    int rm = (tid >> 4) * 8, cn = (tid & 15) * 8;
    uint64_t accp[8][4];                 // rows x packed col-pairs
#pragma unroll
    for (int i = 0; i < 8; i++)
#pragma unroll
        for (int j = 0; j < 4; j++) accp[i][j] = 0ull;

    float4 a0v = *(const float4*)(Ap0);
    float4 a1v = *(const float4*)(Ap1);
    float4 b0v = *(const float4*)(Bp0);
    float4 b1v = *(const float4*)(Bp1);

    for (int k0 = 0; k0 < D_; k0 += 16) {
        As[lk4+0][lr]    = a0v.x; As[lk4+1][lr]    = a0v.y;
        As[lk4+2][lr]    = a0v.z; As[lk4+3][lr]    = a0v.w;
        As[lk4+0][lr+64] = a1v.x; As[lk4+1][lr+64] = a1v.y;
        As[lk4+2][lr+64] = a1v.z; As[lk4+3][lr+64] = a1v.w;
        Bs[lk4+0][lr]    = b0v.x; Bs[lk4+1][lr]    = b0v.y;
        Bs[lk4+2][lr]    = b0v.z; Bs[lk4+3][lr]    = b0v.w;
        Bs[lk4+0][lr+64] = b1v.x; Bs[lk4+1][lr+64] = b1v.y;
        Bs[lk4+2][lr+64] = b1v.z; Bs[lk4+3][lr+64] = b1v.w;
        __syncthreads();

        if (k0 + 16 < D_) {
            a0v = *(const float4*)(Ap0 + k0 + 16);
            a1v = *(const float4*)(Ap1 + k0 + 16);
            b0v = *(const float4*)(Bp0 + k0 + 16);
            b1v = *(const float4*)(Bp1 + k0 + 16);
        }

#pragma unroll
        for (int kk = 0; kk < 16; kk++) {
            float4 x0 = *(const float4*)&As[kk][rm];
            float4 x1 = *(const float4*)&As[kk][rm + 4];
            ulonglong2 yb0 = *(const ulonglong2*)&Bs[kk][cn];
            ulonglong2 yb1 = *(const ulonglong2*)&Bs[kk][cn + 4];
            uint64_t bp0 = yb0.x, bp1 = yb0.y, bp2 = yb1.x, bp3 = yb1.y;
            float av[8] = {x0.x, x0.y, x0.z, x0.w, x1.x, x1.y, x1.z, x1.w};
#pragma unroll
            for (int i = 0; i < 8; i++) {
                uint64_t s = splat2(av[i]);
                ffma2(accp[i][0], s, bp0);
                ffma2(accp[i][1], s, bp1);
                ffma2(accp[i][2], s, bp2);
                ffma2(accp[i][3], s, bp3);
            }
        }
        __syncthreads();
    }

#pragma unroll
    for (int i = 0; i < 8; i++) {
        int mm = m0 + rm + i;
        float4 e0 = *(const float4*)&d_enc_pre[(mm & 31) * G4 + n0 + cn];
        float4 e1 = *(const float4*)&d_enc_pre[(mm & 31) * G4 + n0 + cn + 4];
        float2 p0 = unpack2(accp[i][0]);
        float2 p1 = unpack2(accp[i][1]);
        float2 p2 = unpack2(accp[i][2]);
        float2 p3 = unpack2(accp[i][3]);
        float4 r0 = { p0.x + e0.x, p0.y + e0.y, p1.x + e0.z, p1.y + e0.w };
        float4 r1 = { p2.x + e1.x, p2.y + e1.y, p3.x + e1.z, p3.y + e1.w };
        *(float4*)&d_pre[(size_t)mm * G4 + n0 + cn]     = r0;
        *(float4*)&d_pre[(size_t)mm * G4 + n0 + cn + 4] = r1;
    }
}

// ---------------- persistent recurrence, 512 threads, packed f32x2 --------
__global__ __launch_bounds__(512, 1) void rec_persist(const float* __restrict__ Whh)
{
    extern __shared__ float smem[];
    float* s_hx = smem;             // [32][1024]  128KB
    float* red  = smem + 32768;     // [32][16][32] 64KB

    int tid = threadIdx.x;
    int col = tid & 31;             // gate column within block (g*8+hh)
    int kg  = tid >> 5;             // K-slice 0..15 (64 k each)
    int g   = col >> 3, hh = col & 7;
    int hbase = blockIdx.x * 8;
    int jcol = g * H_ + hbase + hh;

    // W_hh slice packed as fp32 pairs: 64 floats = 16 x ulonglong2
    ulonglong2 w2[16];
    const ulonglong2* wp = (const ulonglong2*)(Whh + (size_t)jcol * H_) + kg * 16;
#pragma unroll
    for (int k = 0; k < 16; k++) w2[k] = wp[k];

    int b_own = tid >> 3, hh_own = tid & 7;   // valid for tid<256
    int hcol_own = hbase + hh_own;
    float creg = 0.f;

    for (int t = 0; t < T_; t++) {
        // prefetch this step's pre-gate values early (independent of hx)
        float p0 = 0.f, p1 = 0.f, p2 = 0.f, p3 = 0.f;
        if (tid < 256) {
            const float* pp = d_pre + ((size_t)(t * B_ + b_own)) * G4 + hcol_own;
            p0 = __ldg(pp);            p1 = __ldg(pp + H_);
            p2 = __ldg(pp + 2 * H_);   p3 = __ldg(pp + 3 * H_);
        }

        const float4* src = (const float4*)(d_hx + (size_t)t * (B_ * H_));
        float4* dst = (float4*)s_hx;
#pragma unroll
        for (int i = 0; i < 16; i++) dst[tid + i * 512] = src[tid + i * 512];
        __syncthreads();

#pragma unroll 2
        for (int b = 0; b < 32; b++) {
            const ulonglong2* hrow = (const ulonglong2*)(s_hx + b * H_ + kg * 64);
            uint64_t acc01 = 0ull, acc23 = 0ull;   // packed (+0,+0)
#pragma unroll
            for (int k = 0; k < 16; k++) {
                ulonglong2 h = hrow[k];
                ffma2(acc01, w2[k].x, h.x);
                ffma2(acc23, w2[k].y, h.y);
            }
            float2 s01 = unpack2(acc01);
            float2 s23 = unpack2(acc23);
            red[b * 512 + kg * 32 + col] = (s01.x + s01.y) + (s23.x + s23.y);
        }
        __syncthreads();

        if (tid < 256) {
            float gi = 0.f, gf = 0.f, gg = 0.f, go = 0.f;
#pragma unroll
            for (int kk = 0; kk < 16; kk++) {
                const float* r = red + b_own * 512 + kk * 32;
                gi += r[hh_own];      gf += r[8  + hh_own];
                gg += r[16 + hh_own]; go += r[24 + hh_own];
            }
            gi += p0; gf += p1; gg += p2; go += p3;
            float si = 1.f / (1.f + expf(-gi));
            float sf = 1.f / (1.f + expf(-gf));
            float so = 1.f / (1.f + expf(-go));
            creg = sf * creg + si * tanhf(gg);
            float hn = so * tanhf(creg);
            d_hx[(size_t)(t + 1) * (B_ * H_) + b_own * H_ + hcol_own] = hn;
            __nv_bfloat16 ah = __float2bfloat16(hn);
            __nv_bfloat16 al = __float2bfloat16(hn - __bfloat162float(ah));
            size_t arow = (size_t)(t * B_ + b_own) * H_ + hcol_own;
            d_Ah[arow] = ah; d_Al[arow] = al;
        }

        __threadfence();
        __syncthreads();
        if (tid == 0) {
            atomicAdd(&g_bar, 1u);
            unsigned target = 128u * (unsigned)(t + 1);
            while (*((volatile unsigned*)&g_bar) < target) { }
        }
        __syncthreads();
    }
}

// ---------------- tensor logits via mma.sync (bf16 hi/lo split) -----------
// out = Ah@Bh^T + Al@Bh^T + Ah@Bl^T + b_fc. CTA 128x128, 8 warps (4m x 2n),
// warp tile 32x64, BK=32, double-buffered padded smem, reg prefetch,
// 1 sync/k-tile. Fused per-row argmax via packed atomicMax.
#define PAD_ 40
__global__ __launch_bounds__(256, 2) void logits_mma(
    const float* __restrict__ bfc, float* __restrict__ out)
{
    __shared__ __align__(16) __nv_bfloat16 sA[2][128 * PAD_];
    __shared__ __align__(16) __nv_bfloat16 sB[2][128 * PAD_];

    int tid = threadIdx.x, lane = tid & 31, w = tid >> 5;
    int wm = w & 3, wn = w >> 2;
    int m0 = blockIdx.x * 128, n0 = blockIdx.y * 128;

    float c[2][8][4];
#pragma unroll
    for (int mi = 0; mi < 2; mi++)
#pragma unroll
        for (int ni = 0; ni < 8; ni++)
#pragma unroll
            for (int q = 0; q < 4; q++) c[mi][ni][q] = 0.f;

    int lrow = tid >> 2, lch = (tid & 3) * 8;      // loader: 2 chunks/thread

    uint4 pa[2], pb[2];
    {   // prefetch iteration 0 (seg 0, k0 0)
#pragma unroll
        for (int i = 0; i < 2; i++) {
            int row = lrow + i * 64;
            pa[i] = *(const uint4*)(d_Ah + (size_t)(m0 + row) * H_ + lch);
            pb[i] = *(const uint4*)(d_Bh + (size_t)(n0 + row) * H_ + lch);
        }
    }

    // ldsm lane addressing
    int a_col_l = (lane >> 4) * 8;
    int b_row_l = wn * 64 + ((lane >> 4) & 1) * 8 + (lane & 7);
    int b_col_l = ((lane >> 3) & 1) * 8;

    int buf = 0;
    for (int it = 0; it < 96; it++) {
        // store prefetched tile
#pragma unroll
        for (int i = 0; i < 2; i++) {
            int row = lrow + i * 64;
            *(uint4*)(&sA[buf][row * PAD_ + lch]) = pa[i];
            *(uint4*)(&sB[buf][row * PAD_ + lch]) = pb[i];
        }
        __syncthreads();

        // prefetch next k-tile while computing
        if (it + 1 < 96) {
            int nit = it + 1;
            int seg = nit >> 5;                 // 0..2
            int k0  = (nit & 31) * 32;
            const __nv_bfloat16* As = (seg == 1) ? d_Al : d_Ah;
            const __nv_bfloat16* Bs = (seg == 2) ? d_Bl : d_Bh;
#pragma unroll
            for (int i = 0; i < 2; i++) {
                int row = lrow + i * 64;
                pa[i] = *(const uint4*)(As + (size_t)(m0 + row) * H_ + k0 + lch);
                pb[i] = *(const uint4*)(Bs + (size_t)(n0 + row) * H_ + k0 + lch);
            }
        }

        // compute: 2 k16 steps
#pragma unroll
        for (int ks = 0; ks < 2; ks++) {
            uint32_t af[2][4];
#pragma unroll
            for (int mi = 0; mi < 2; mi++) {
                int row = wm * 32 + mi * 16 + (lane & 15);
                uint32_t a = smem_u32(&sA[buf][row * PAD_ + ks * 16 + a_col_l]);
                ldsm_x4(af[mi][0], af[mi][1], af[mi][2], af[mi][3], a);
            }
#pragma unroll
            for (int np = 0; np < 4; np++) {
                uint32_t b0, b1, b2, b3;
                uint32_t ba = smem_u32(
                    &sB[buf][(b_row_l + np * 16) * PAD_ + ks * 16 + b_col_l]);
                ldsm_x4(b0, b1, b2, b3, ba);
#pragma unroll
                for (int mi = 0; mi < 2; mi++) {
                    mma16816(c[mi][np * 2],     af[mi][0], af[mi][1], af[mi][2], af[mi][3], b0, b1);
                    mma16816(c[mi][np * 2 + 1], af[mi][0], af[mi][1], af[mi][2], af[mi][3], b2, b3);
                }
            }
        }
        buf ^= 1;
    }

    // epilogue: acc m16n8 -> (row lane>>2 [+8], col (lane&3)*2 [+1])
    // fused per-row argmax: best over this thread's 16 cols, shfl-reduce
    // across the 4-lane quad group, atomicMax into d_amax[row].
#pragma unroll
    for (int mi = 0; mi < 2; mi++) {
        unsigned long long key0 = 0ull, key1 = 0ull;   // rows r0, r0+8
        int rbase = m0 + wm * 32 + mi * 16 + (lane >> 2);
#pragma unroll
        for (int ni = 0; ni < 8; ni++) {
            int col = n0 + wn * 64 + ni * 8 + (lane & 3) * 2;
            float2 bb = *(const float2*)&bfc[col];
            float2 r0 = { c[mi][ni][0] + bb.x, c[mi][ni][1] + bb.y };
            float2 r1 = { c[mi][ni][2] + bb.x, c[mi][ni][3] + bb.y };
            *(float2*)&out[(size_t)rbase * V_ + col]       = r0;
            *(float2*)&out[(size_t)(rbase + 8) * V_ + col] = r1;
            unsigned long long k;
            k = ((unsigned long long)fmono(r0.x) << 32) | (uint32_t)~col;
            if (k > key0) key0 = k;
            k = ((unsigned long long)fmono(r0.y) << 32) | (uint32_t)~(col + 1);
            if (k > key0) key0 = k;
            k = ((unsigned long long)fmono(r1.x) << 32) | (uint32_t)~col;
            if (k > key1) key1 = k;
            k = ((unsigned long long)fmono(r1.y) << 32) | (uint32_t)~(col + 1);
            if (k > key1) key1 = k;
        }
        // reduce across the 4 lanes sharing each row
#pragma unroll
        for (int s = 1; s < 4; s <<= 1) {
            unsigned long long o0 = __shfl_xor_sync(0xFFFFFFFFu, key0, s);
            unsigned long long o1 = __shfl_xor_sync(0xFFFFFFFFu, key1, s);
            if (o0 > key0) key0 = o0;
            if (o1 > key1) key1 = o1;
        }
        if ((lane & 3) == 0) {
            atomicMax(&d_amax[rbase], key0);
            atomicMax(&d_amax[rbase + 8], key1);
        }
    }
}

// ---------------- finalize predic from packed argmax ----------------------
__global__ __launch_bounds__(256) void pred_finalize(float* __restrict__ pred)
{
    int m = blockIdx.x * 256 + threadIdx.x;
    if (m >= TB) return;
    unsigned col = ~(unsigned)(d_amax[m] & 0xFFFFFFFFull);
    int t = m >> 5, b = m & 31;
    pred[b * T_ + t] = (float)col;
}

// ------------------------------------------------------------------------
extern "C" void kernel_launch(void* const* d_in, const int* in_sizes, int n_in,
                              void* d_out, int out_size)
{
    const float* encoder = (const float*)d_in[0];
    const int*   gtruths = (const int*)  d_in[1];
    const float* emb     = (const float*)d_in[2];
    const float* W_ih    = (const float*)d_in[3];
    const float* W_hh    = (const float*)d_in[4];
    const float* b_ih    = (const float*)d_in[5];
    const float* b_hh    = (const float*)d_in[6];
    const float* W_fc    = (const float*)d_in[7];
    const float* b_fc    = (const float*)d_in[8];
    float* out = (float*)d_out;

    static int attr_set = 0;
    if (!attr_set) {
        cudaFuncSetAttribute(rec_persist,
                             cudaFuncAttributeMaxDynamicSharedMemorySize, 196608);
        attr_set = 1;
    }

    init_state<<<(B_ * H_ + 255) / 256, 256>>>();
    conv_wfc<<<(int)(((size_t)V_ * H_ / 4) / 256), 256>>>(W_fc);
    enc_pre_kernel<<<G4 / 32, 256>>>(encoder, W_ih, b_ih, b_hh);
    pre_gemm_big<<<dim3(TB / 128, G4 / 128), 256>>>(emb, gtruths, W_ih);
    rec_persist<<<128, 512, 196608>>>(W_hh);
    logits_mma<<<dim3(TB / 128, V_ / 128), 256>>>(b_fc, out);
    if (out_size >= TB * V_ + TB)
        pred_finalize<<<(TB + 255) / 256, 256>>>(out + (size_t)TB * V_);
}